// round 5
// baseline (speedup 1.0000x reference)
#include <cuda_runtime.h>
#include <cstdint>

// resRNN: x(256,1024,8), W1(521,512), b1(512), W2(512,1), b2(1)
// out = [output(256,1024,1) | implied_storage(256,1024,1)]
//
// 128 CTAs = 16 rowgroups x 8 colgroups. Cluster(8) = one rowgroup.
// Each CTA: 16 batch rows x 64 hidden cols, W1 slice resident in smem.
// 16 warps = 8 k-parts x 2 row-halves; fma.rn.f32x2 packed accumulators.

#define TPB 512

static __device__ float g_hx[2][256][512];       // double-buffered hidden state
static __device__ float g_part[2][16][8][16];    // per-(rg,cg,row) readout partials

// shared memory layout (float offsets)
#define OFF_W    0              // 544*64   = 34816 floats
#define OFF_IT   34816          // 544*18   =  9792 floats (inpT[k][16], stride 18)
#define OFF_RED  44608          // 8*16*68  =  8704 floats
#define OFF_B1   53312          // 64
#define OFF_W2   53376          // 64
#define OFF_S    53440          // 16
#define OFF_OUT  53456          // 16
#define SMEM_FLOATS 53472
#define SMEM_BYTES (SMEM_FLOATS * 4)

__global__ void __cluster_dims__(8, 1, 1) __launch_bounds__(512, 1)
resRNN_kernel(const float* __restrict__ x, const float* __restrict__ W1,
              const float* __restrict__ b1, const float* __restrict__ W2,
              const float* __restrict__ b2, float* __restrict__ dout)
{
    extern __shared__ float sm[];
    float* Wsm    = sm + OFF_W;
    float* inpT   = sm + OFF_IT;
    float* red    = sm + OFF_RED;
    float* b1s    = sm + OFF_B1;
    float* w2s    = sm + OFF_W2;
    float* s_sm   = sm + OFF_S;
    float* out_sm = sm + OFF_OUT;

    const int tid  = threadIdx.x;
    const int warp = tid >> 5;
    const int lane = tid & 31;
    const int kp   = warp & 7;     // k-partition 0..7
    const int h    = warp >> 3;    // row-half 0..1
    const int cg   = blockIdx.x;   // colgroup 0..7
    const int rg   = blockIdx.y;   // rowgroup 0..15
    const int row0 = rg * 16;

    // ---- init: load W1 slice [544 x 64] (zero-pad k>=521), zero inpT ----
    for (int i = tid; i < 544 * 16; i += TPB) {
        int k = i >> 4, f4 = i & 15;
        float4 v = make_float4(0.f, 0.f, 0.f, 0.f);
        if (k < 521) v = *(const float4*)&W1[k * 512 + cg * 64 + f4 * 4];
        *(float4*)&Wsm[k * 64 + f4 * 4] = v;
    }
    for (int i = tid; i < 544 * 18; i += TPB) inpT[i] = 0.f;
    if (tid < 64) { b1s[tid] = b1[cg * 64 + tid]; w2s[tid] = W2[cg * 64 + tid]; }
    if (tid < 16) { s_sm[tid] = 0.f; out_sm[tid] = 0.f; }
    const float b2v = b2[0];
    float* outp = dout;
    float* stop = dout + 256 * 1024;

    // x prefetch registers (threads 0..127 own (row r = tid>>3, comp = tid&7);
    // threads 0..15 additionally own x0 of their row for the mass balance)
    const int xr = tid >> 3, xc = tid & 7;
    float xpre = 0.f, x0pre = 0.f;
    if (tid < 128) xpre  = x[(row0 + xr) * 8192 + xc];
    if (tid < 16)  x0pre = x[(row0 + tid) * 8192];
    __syncthreads();

    for (int t = 0; t < 1024; ++t) {
        const int pw = t & 1;        // write parity
        const int pr = pw ^ 1;       // read parity = (t-1)&1

        // ---- Phase A: gather out_{t-1}; transpose hx into inpT; stage x_t ----
        if (t > 0) {
            if (tid < 16) {
                float o = b2v;
                #pragma unroll
                for (int g = 0; g < 8; ++g) o += __ldcg(&g_part[pr][rg][g][tid]);
                out_sm[tid] = o;
                // mass balance: s_t = s_{t-1} + x_t[0] - out_{t-1}
                float s = s_sm[tid] + x0pre - o;
                s_sm[tid] = s;
                inpT[8 * 18 + tid] = s;
                if (cg == 0) {
                    outp[(row0 + tid) * 1024 + (t - 1)] = o;
                    stop[(row0 + tid) * 1024 + t] = s;
                }
            }
            // hx transpose: thread tid (0..511) owns hidden column tid.
            // Row stride 18 floats => base offset only 8B-aligned: use float2 stores.
            float v[16];
            #pragma unroll
            for (int r = 0; r < 16; ++r) v[r] = __ldcg(&g_hx[pr][row0 + r][tid]);
            float* dst = &inpT[(9 + tid) * 18];
            #pragma unroll
            for (int q = 0; q < 8; ++q)
                *(float2*)(dst + 2 * q) = make_float2(v[2*q], v[2*q+1]);
        } else {
            if (tid < 16) {
                float s = x0pre;                 // s_0 = x_0[0] (prev out = 0)
                s_sm[tid] = s;
                inpT[8 * 18 + tid] = s;
                if (cg == 0) stop[(row0 + tid) * 1024] = s;
            }
        }
        if (tid < 128) inpT[xc * 18 + xr] = xpre;
        // prefetch x_{t+1} (overlaps with mainloop)
        if (t < 1023) {
            if (tid < 128) xpre  = x[(row0 + xr) * 8192 + (t + 1) * 8 + xc];
            if (tid < 16)  x0pre = x[(row0 + tid) * 8192 + (t + 1) * 8];
        }
        __syncthreads();

        // ---- Phase C: mainloop. warp (kp,h): k in [kp*68, kp*68+68), rows h*8..h*8+7
        unsigned long long acc[8];
        #pragma unroll
        for (int i = 0; i < 8; ++i) acc[i] = 0ull;
        {
            const float* Ip = inpT + kp * 68 * 18 + h * 8;
            const float* Wp = Wsm + kp * 68 * 64 + 2 * lane;
            #pragma unroll 4
            for (int kk = 0; kk < 68; ++kk) {
                unsigned long long ip[4];
                #pragma unroll
                for (int j = 0; j < 4; ++j)
                    ip[j] = *(const unsigned long long*)(Ip + kk * 18 + 2 * j);
                float2 wv = *(const float2*)(Wp + kk * 64);
                unsigned long long w00, w11;
                asm("mov.b64 %0, {%1, %1};" : "=l"(w00) : "f"(wv.x));
                asm("mov.b64 %0, {%1, %1};" : "=l"(w11) : "f"(wv.y));
                #pragma unroll
                for (int rp = 0; rp < 4; ++rp) {
                    asm("fma.rn.f32x2 %0, %1, %2, %0;" : "+l"(acc[2 * rp])     : "l"(ip[rp]), "l"(w00));
                    asm("fma.rn.f32x2 %0, %1, %2, %0;" : "+l"(acc[2 * rp + 1]) : "l"(ip[rp]), "l"(w11));
                }
            }
        }

        // ---- Phase D: spill k-partials, reduce, tanh, emit hx + readout partial
        #pragma unroll
        for (int rp = 0; rp < 4; ++rp) {
            float2 a0 = *(float2*)&acc[2 * rp];       // rows (h8+2rp, h8+2rp+1), col 2*lane
            float2 a1 = *(float2*)&acc[2 * rp + 1];   // col 2*lane+1
            int r = h * 8 + 2 * rp;
            *(float2*)&red[(kp * 16 + r)     * 68 + 2 * lane] = make_float2(a0.x, a1.x);
            *(float2*)&red[(kp * 16 + r + 1) * 68 + 2 * lane] = make_float2(a0.y, a1.y);
        }
        __syncthreads();
        {
            // warp w handles row w (16 warps = 16 rows); lane handles cols 2*lane, 2*lane+1
            int r = warp, c2 = 2 * lane;
            float2 v = make_float2(0.f, 0.f);
            #pragma unroll
            for (int w = 0; w < 8; ++w) {
                float2 p = *(const float2*)&red[(w * 16 + r) * 68 + c2];
                v.x += p.x; v.y += p.y;
            }
            v.x = tanhf(v.x + b1s[c2]);
            v.y = tanhf(v.y + b1s[c2 + 1]);
            *(float2*)&g_hx[pw][row0 + r][cg * 64 + c2] = v;
            float p = v.x * w2s[c2] + v.y * w2s[c2 + 1];
            #pragma unroll
            for (int off = 16; off > 0; off >>= 1)
                p += __shfl_xor_sync(0xffffffffu, p, off);
            if (lane == 0) g_part[pw][rg][cg][r] = p;
        }

        // ---- Phase E: cluster barrier (release on arrive / acquire on wait) ----
        asm volatile("barrier.cluster.arrive.aligned;" ::: "memory");
        asm volatile("barrier.cluster.wait.aligned;" ::: "memory");
    }

    // epilogue: final output value out_{L-1}
    if (cg == 0 && tid < 16) {
        float o = b2v;
        #pragma unroll
        for (int g = 0; g < 8; ++g) o += __ldcg(&g_part[1][rg][g][tid]);
        outp[(row0 + tid) * 1024 + 1023] = o;
    }
}

extern "C" void kernel_launch(void* const* d_in, const int* in_sizes, int n_in,
                              void* d_out, int out_size) {
    const float* x  = (const float*)d_in[0];
    const float* W1 = (const float*)d_in[1];
    const float* b1 = (const float*)d_in[2];
    const float* W2 = (const float*)d_in[3];
    const float* b2 = (const float*)d_in[4];
    float* out = (float*)d_out;

    cudaFuncSetAttribute(resRNN_kernel, cudaFuncAttributeMaxDynamicSharedMemorySize, SMEM_BYTES);

    dim3 grid(8, 16, 1);   // cluster_dims (8,1,1): one cluster per rowgroup
    dim3 block(TPB, 1, 1);
    resRNN_kernel<<<grid, block, SMEM_BYTES>>>(x, W1, b1, W2, b2, out);
}

// round 7
// speedup vs baseline: 1.2034x; 1.2034x over previous
#include <cuda_runtime.h>
#include <cstdint>
#include <cstdio>

// resRNN: x(256,1024,8), W1(521,512), b1(512), W2(512,1), b2(1)
// out = [output(256,1024,1) | implied_storage(256,1024,1)]
//
// 128 CTAs = 16 rowgroups x 8 colgroups. Cluster(8) = one rowgroup.
// Each CTA: 16 batch rows x 64 hidden cols, W1 slice resident in smem.
// 8 warps = 8 k-parts (68 k each); lane = col-pair; fma.rn.f32x2 accumulators.

#define TPB 256

static __device__ float g_hx[2][256][512];       // double-buffered hidden state
static __device__ float g_part[2][16][8][16];    // per-(rg,cg,row) readout partials

// shared memory layout (float offsets); inpT stride = 20 (16 rows + 4 pad, 16B-aligned quads)
#define OFF_W    0              // 544*64   = 34816 floats
#define OFF_IT   34816          // 544*20   = 10880 floats (inpT[k][20])
#define OFF_RED  45696          // 8*16*68  =  8704 floats
#define OFF_B1   54400          // 64
#define OFF_W2   54464          // 64
#define OFF_S    54528          // 16
#define SMEM_FLOATS 54544
#define SMEM_BYTES (SMEM_FLOATS * 4)

__global__ void __cluster_dims__(8, 1, 1) __launch_bounds__(256, 1)
resRNN_kernel(const float* __restrict__ x, const float* __restrict__ W1,
              const float* __restrict__ b1, const float* __restrict__ W2,
              const float* __restrict__ b2, float* __restrict__ dout)
{
    extern __shared__ float sm[];
    float* Wsm  = sm + OFF_W;
    float* inpT = sm + OFF_IT;
    float* red  = sm + OFF_RED;
    float* b1s  = sm + OFF_B1;
    float* w2s  = sm + OFF_W2;
    float* s_sm = sm + OFF_S;

    const int tid  = threadIdx.x;
    const int warp = tid >> 5;     // k-partition 0..7
    const int lane = tid & 31;
    const int cg   = blockIdx.x;   // colgroup 0..7
    const int rg   = blockIdx.y;   // rowgroup 0..15
    const int row0 = rg * 16;

    // ---- init: load W1 slice [544 x 64] (zero-pad k>=521), zero inpT ----
    for (int i = tid; i < 544 * 16; i += TPB) {
        int k = i >> 4, f4 = i & 15;
        float4 v = make_float4(0.f, 0.f, 0.f, 0.f);
        if (k < 521) v = *(const float4*)&W1[k * 512 + cg * 64 + f4 * 4];
        *(float4*)&Wsm[k * 64 + f4 * 4] = v;
    }
    for (int i = tid; i < 544 * 20; i += TPB) inpT[i] = 0.f;
    if (tid < 64) { b1s[tid] = b1[cg * 64 + tid]; w2s[tid] = W2[cg * 64 + tid]; }
    const float b2v = b2[0];
    float* outp = dout;
    float* stop = dout + 256 * 1024;

    // pre-loop: stage x_0 into inpT, s_0 = x_0[0]; prefetch x_1
    const int xr = tid >> 3, xc = tid & 7;
    float xpre = 0.f, x0pre = 0.f;
    if (tid < 128) {
        float xv = x[(row0 + xr) * 8192 + xc];
        inpT[xc * 20 + xr] = xv;
        xpre = x[(row0 + xr) * 8192 + 8 + xc];         // x_1
    }
    if (tid < 16) {
        float s = x[(row0 + tid) * 8192];              // s_0 = x_0[0] (prev out = 0)
        s_sm[tid] = s;
        inpT[8 * 20 + tid] = s;
        if (cg == 0) stop[(row0 + tid) * 1024] = s;
        x0pre = x[(row0 + tid) * 8192 + 8];            // x_1[0] (for Phase A at t=1)
    }
    __syncthreads();

    long long tA = 0, tM = 0, tR = 0, tX = 0, tW = 0;

    for (int t = 0; t < 1024; ++t) {
        const int pw = t & 1;        // write parity
        const int pr = pw ^ 1;       // read parity = (t-1)&1

        long long c0 = clock64();

        // ---- Phase A: gather out_{t-1}; mass balance; transpose hx into inpT ----
        if (t > 0) {
            if (tid < 16) {
                float o = b2v;
                #pragma unroll
                for (int g = 0; g < 8; ++g) o += __ldcg(&g_part[pr][rg][g][tid]);
                // s_t = s_{t-1} + x_t[0] - out_{t-1}
                float s = s_sm[tid] + x0pre - o;
                s_sm[tid] = s;
                inpT[8 * 20 + tid] = s;
                if (cg == 0) {
                    outp[(row0 + tid) * 1024 + (t - 1)] = o;
                    stop[(row0 + tid) * 1024 + t] = s;
                }
            }
            // hx transpose: thread owns hidden cols tid and tid+256
            float v0[16], v1[16];
            #pragma unroll
            for (int r = 0; r < 16; ++r) v0[r] = __ldcg(&g_hx[pr][row0 + r][tid]);
            #pragma unroll
            for (int r = 0; r < 16; ++r) v1[r] = __ldcg(&g_hx[pr][row0 + r][tid + 256]);
            float* d0 = &inpT[(9 + tid) * 20];
            float* d1 = &inpT[(9 + tid + 256) * 20];
            #pragma unroll
            for (int q = 0; q < 8; ++q) {
                *(float2*)(d0 + 2 * q) = make_float2(v0[2*q], v0[2*q+1]);
                *(float2*)(d1 + 2 * q) = make_float2(v1[2*q], v1[2*q+1]);
            }
        }
        __syncthreads();
        long long c1 = clock64();

        // ---- Phase C: mainloop. warp kp: k in [kp*68, kp*68+68), all 16 rows,
        //      cols (2*lane, 2*lane+1). acc0 = col even, acc1 = col odd; pairs of rows.
        unsigned long long acc0[8], acc1[8];
        #pragma unroll
        for (int i = 0; i < 8; ++i) { acc0[i] = 0ull; acc1[i] = 0ull; }
        {
            const float* Ip = inpT + warp * 68 * 20;
            const float* Wp = Wsm + warp * 68 * 64 + 2 * lane;
            #pragma unroll 4
            for (int kk = 0; kk < 68; ++kk) {
                unsigned long long pr_[8];
                #pragma unroll
                for (int j = 0; j < 4; ++j) {
                    ulonglong2 q = *(const ulonglong2*)(Ip + kk * 20 + 4 * j);
                    pr_[2 * j] = q.x; pr_[2 * j + 1] = q.y;
                }
                float2 wv = *(const float2*)(Wp + kk * 64);
                unsigned long long w00, w11;
                asm("mov.b64 %0, {%1, %1};" : "=l"(w00) : "f"(wv.x));
                asm("mov.b64 %0, {%1, %1};" : "=l"(w11) : "f"(wv.y));
                #pragma unroll
                for (int p = 0; p < 8; ++p) {
                    asm("fma.rn.f32x2 %0, %1, %2, %0;" : "+l"(acc0[p]) : "l"(pr_[p]), "l"(w00));
                    asm("fma.rn.f32x2 %0, %1, %2, %0;" : "+l"(acc1[p]) : "l"(pr_[p]), "l"(w11));
                }
            }
        }
        long long c2 = clock64();

        // ---- Phase D: spill k-partials, reduce, tanh, emit hx + readout partial ----
        #pragma unroll
        for (int p = 0; p < 8; ++p) {
            float2 a0 = *(float2*)&acc0[p];   // (row 2p, row 2p+1) col even
            float2 a1 = *(float2*)&acc1[p];   // col odd
            *(float2*)&red[(warp * 16 + 2 * p)     * 68 + 2 * lane] = make_float2(a0.x, a1.x);
            *(float2*)&red[(warp * 16 + 2 * p + 1) * 68 + 2 * lane] = make_float2(a0.y, a1.y);
        }
        __syncthreads();
        {
            int r = tid >> 4, c4 = (tid & 15) * 4;
            float4 v = make_float4(0.f, 0.f, 0.f, 0.f);
            #pragma unroll
            for (int w = 0; w < 8; ++w) {
                float4 p = *(const float4*)&red[(w * 16 + r) * 68 + c4];
                v.x += p.x; v.y += p.y; v.z += p.z; v.w += p.w;
            }
            v.x = tanhf(v.x + b1s[c4 + 0]);
            v.y = tanhf(v.y + b1s[c4 + 1]);
            v.z = tanhf(v.z + b1s[c4 + 2]);
            v.w = tanhf(v.w + b1s[c4 + 3]);
            *(float4*)&g_hx[pw][row0 + r][cg * 64 + c4] = v;
            float p = v.x * w2s[c4] + v.y * w2s[c4 + 1] + v.z * w2s[c4 + 2] + v.w * w2s[c4 + 3];
            #pragma unroll
            for (int off = 8; off > 0; off >>= 1)
                p += __shfl_xor_sync(0xffffffffu, p, off);
            if ((tid & 15) == 0) g_part[pw][rg][cg][r] = p;
        }
        long long c3 = clock64();

        // ---- Phase E: split cluster barrier; x staging hides in the gap ----
        asm volatile("barrier.cluster.arrive.aligned;" ::: "memory");
        if (t < 1023) {
            if (tid < 128) {
                inpT[xc * 20 + xr] = xpre;                           // stage x_{t+1}
                if (t < 1022) xpre = x[(row0 + xr) * 8192 + (t + 2) * 8 + xc];
            }
            // x0 for next step's Phase A = x_{t+1}[0]; loaded in the gap,
            // latency covered by the barrier wait.
            if (tid < 16) x0pre = x[(row0 + tid) * 8192 + (t + 1) * 8];
        }
        long long c4 = clock64();
        asm volatile("barrier.cluster.wait.aligned;" ::: "memory");
        long long c5 = clock64();

        tA += c1 - c0; tM += c2 - c1; tR += c3 - c2; tX += c4 - c3; tW += c5 - c4;
    }

    // epilogue: final output value out_{L-1}
    if (cg == 0 && tid < 16) {
        float o = b2v;
        #pragma unroll
        for (int g = 0; g < 8; ++g) o += __ldcg(&g_part[1][rg][g][tid]);
        outp[(row0 + tid) * 1024 + 1023] = o;
    }

    if (blockIdx.x == 0 && blockIdx.y == 0 && tid == 0) {
        printf("PHASES cyc/step: A=%lld M=%lld R=%lld X=%lld W=%lld tot=%lld\n",
               tA / 1024, tM / 1024, tR / 1024, tX / 1024, tW / 1024,
               (tA + tM + tR + tX + tW) / 1024);
    }
}

extern "C" void kernel_launch(void* const* d_in, const int* in_sizes, int n_in,
                              void* d_out, int out_size) {
    const float* x  = (const float*)d_in[0];
    const float* W1 = (const float*)d_in[1];
    const float* b1 = (const float*)d_in[2];
    const float* W2 = (const float*)d_in[3];
    const float* b2 = (const float*)d_in[4];
    float* out = (float*)d_out;

    cudaFuncSetAttribute(resRNN_kernel, cudaFuncAttributeMaxDynamicSharedMemorySize, SMEM_BYTES);

    dim3 grid(8, 16, 1);   // cluster_dims (8,1,1): one cluster per rowgroup
    dim3 block(TPB, 1, 1);
    resRNN_kernel<<<grid, block, SMEM_BYTES>>>(x, W1, b1, W2, b2, out);
}